// round 7
// baseline (speedup 1.0000x reference)
#include <cuda_runtime.h>
#include <math.h>
#include <limits.h>

// CRF loss: out[b] = logZ(b) - label_score(b).  B=512, S=512, L=128.
//
// Scaled linear-space forward recursion. Grid sized so every SM holds
// exactly 2 CTAs (296 blocks for B=512): the 80 longest sequences run as
// single-batch blocks (they are the serial critical path), the remaining
// 432 are paired longest-with-shortest so per-block work is even.
// Thread j holds the full column j of E=exp(trans) as 64 f32x2 regs and
// runs both batches' GEMVs as interleaved FFMA2 chains. U double-buffered
// in shared, ONE __syncthreads per step; rcp/exp/log off the FFMA chain.

#define LDIM 128

__device__ int d_perm[1024];

__device__ __forceinline__ unsigned long long pack_f32x2(float lo, float hi) {
    unsigned long long r;
    asm("mov.b64 %0, {%1, %2};" : "=l"(r) : "f"(lo), "f"(hi));
    return r;
}
__device__ __forceinline__ void unpack_f32x2(unsigned long long v, float& lo, float& hi) {
    asm("mov.b64 {%0, %1}, %2;" : "=f"(lo), "=f"(hi) : "l"(v));
}
__device__ __forceinline__ unsigned long long fma_f32x2(unsigned long long a,
                                                        unsigned long long b,
                                                        unsigned long long c) {
    unsigned long long d;
    asm("fma.rn.f32x2 %0, %1, %2, %3;" : "=l"(d) : "l"(a), "l"(b), "l"(c));
    return d;
}
__device__ __forceinline__ unsigned long long add_f32x2(unsigned long long a,
                                                        unsigned long long b) {
    unsigned long long d;
    asm("add.rn.f32x2 %0, %1, %2;" : "=l"(d) : "l"(a), "l"(b));
    return d;
}
__device__ __forceinline__ float rcp_approx(float x) {
    float r;
    asm("rcp.approx.ftz.f32 %0, %1;" : "=f"(r) : "f"(x));
    return r;
}

// ------------- longest-first permutation (bitonic, 1 block) ---------------
__global__ void sort_len_kernel(const int* __restrict__ length, int B, int S)
{
    __shared__ int key[1024];
    __shared__ int val[1024];
    const int t = threadIdx.x;

    int k = INT_MAX;
    if (t < B) {
        int L = length[t];
        L = L < 1 ? 1 : (L > S ? S : L);
        k = -L;               // ascending on -len => longest first
    }
    key[t] = k;
    val[t] = t;
    __syncthreads();

    for (int kk = 2; kk <= 1024; kk <<= 1) {
        for (int s = kk >> 1; s > 0; s >>= 1) {
            int p = t ^ s;
            if (p > t) {
                bool up = ((t & kk) == 0);
                int kt = key[t], kp = key[p];
                if ((kt > kp) == up) {
                    key[t] = kp; key[p] = kt;
                    int vt = val[t]; val[t] = val[p]; val[p] = vt;
                }
            }
            __syncthreads();
        }
    }
    if (t < B) d_perm[t] = val[t];
}

// ------------------------------ main kernel --------------------------------
__global__ __launch_bounds__(128, 2)
void crf_forward_kernel(const float* __restrict__ input,
                        const int*   __restrict__ label,
                        const int*   __restrict__ length,
                        const float* __restrict__ trans,
                        float* __restrict__ out,
                        int S, int B, int nsingle)
{
    __shared__ __align__(16) float u_sh[2][2][LDIM];   // [buf][g][state]
    __shared__ float wred[2][4];
    __shared__ float wlog[2][4];
    __shared__ float s_x00[2];
    __shared__ float s_ls[2];

    const int tid = threadIdx.x;      // == state column j
    const int j   = tid;
    const int w   = tid >> 5;
    const int l   = tid & 31;

    const int bid = blockIdx.x;
    const bool has_b1 = (bid >= nsingle);
    // singles take sorted ranks [0, nsingle); pair p = bid - nsingle takes
    // ranks nsingle+p (long) and B-1-p (short).
    const int b0 = d_perm[bid];
    const int b1 = has_b1 ? d_perm[B - 1 - (bid - nsingle)] : b0;

    int len0 = length[b0]; len0 = len0 < 1 ? 1 : (len0 > S ? S : len0);
    int len1 = 1;
    if (has_b1) { len1 = length[b1]; len1 = len1 < 1 ? 1 : (len1 > S ? S : len1); }
    // sorted order guarantees len0 >= len1 for pairs.

    const float* xb0 = input + (size_t)b0 * S * LDIM;
    const float* xb1 = input + (size_t)b1 * S * LDIM;

    // ---------------- label scores (both batches) ----------------------
    #pragma unroll
    for (int g = 0; g < 2; g++) {
        const float* xb = g ? xb1 : xb0;
        const int* labb = label + (size_t)(g ? b1 : b0) * S;
        const int  len  = (g ? (has_b1 ? len1 : 0) : len0);
        float ls = 0.f;
        for (int t = tid; t < len; t += LDIM) {
            int lab = labb[t];
            ls += xb[(size_t)t * LDIM + lab];
            if (t + 1 < len) ls += trans[lab * LDIM + labb[t + 1]];
        }
        #pragma unroll
        for (int o = 16; o > 0; o >>= 1)
            ls += __shfl_xor_sync(0xffffffffu, ls, o);
        if (l == 0) wred[g][w] = ls;
    }
    __syncthreads();
    if (tid < 2)
        s_ls[tid] = (wred[tid][0] + wred[tid][1]) + (wred[tid][2] + wred[tid][3]);

    // -------- full column j of E: 64 f32x2 registers -------------------
    unsigned long long E2[64];
    #pragma unroll
    for (int k = 0; k < 64; k++) {
        float lo = __expf(trans[(2 * k)     * LDIM + j]);
        float hi = __expf(trans[(2 * k + 1) * LDIM + j]);
        E2[k] = pack_f32x2(lo, hi);
    }

    // ---------------- init U and prefetch pipeline ----------------------
    float x0_0 = xb0[j];
    float x0_1 = xb1[j];
    if (tid == 0) { s_x00[0] = x0_0; s_x00[1] = x0_1; }   // j==0 values
    __syncthreads();
    const float X00 = s_x00[0];
    const float X01 = s_x00[1];
    float U0 = __expf(x0_0 - X00);
    float U1 = __expf(x0_1 - X01);
    u_sh[0][0][j] = U0;
    u_sh[0][1][j] = U1;

    const float* xend0 = xb0 + (size_t)(len0 - 1) * LDIM + j;
    const float* xend1 = xb1 + (size_t)(len1 - 1) * LDIM + j;
    const float* xp0 = xb0 + j + LDIM; if (xp0 > xend0) xp0 = xend0;
    const float* xp1 = xb1 + j + LDIM; if (xp1 > xend1) xp1 = xend1;
    float xA0 = *xp0, xA1 = *xp1;                  // x for t=1
    xp0 += LDIM; if (xp0 > xend0) xp0 = xend0;
    xp1 += LDIM; if (xp1 > xend1) xp1 = xend1;
    float xB0 = *xp0, xB1 = *xp1;                  // x for t=2

    float alog0 = 0.f, alog1 = 0.f;                // rotating owners only
    __syncthreads();

    int cur = 0;
    int t = 1;

    // ---------------- loop A: both batches active (t < len1) ------------
    for (; t < len1; t++) {
        const int nxt = cur ^ 1;
        const float r0  = rcp_approx(u_sh[cur][0][0]);
        const float r1  = rcp_approx(u_sh[cur][1][0]);
        const float ex0 = __expf(xA0);
        const float ex1 = __expf(xA1);

        xA0 = xB0; xA1 = xB1;
        xp0 += LDIM; if (xp0 > xend0) xp0 = xend0;
        xp1 += LDIM; if (xp1 > xend1) xp1 = xend1;
        xB0 = *xp0; xB1 = *xp1;

        const ulonglong2* p0 = (const ulonglong2*)u_sh[cur][0];
        const ulonglong2* p1 = (const ulonglong2*)u_sh[cur][1];
        unsigned long long a0 = 0ull, a1 = 0ull, a2 = 0ull, a3 = 0ull;
        unsigned long long c0 = 0ull, c1 = 0ull, c2 = 0ull, c3 = 0ull;
        #pragma unroll
        for (int k = 0; k < 32; k += 2) {
            ulonglong2 ua = p0[k];
            ulonglong2 ub = p0[k + 1];
            ulonglong2 va = p1[k];
            ulonglong2 vb = p1[k + 1];
            a0 = fma_f32x2(ua.x, E2[2 * k + 0], a0);
            a1 = fma_f32x2(ua.y, E2[2 * k + 1], a1);
            c0 = fma_f32x2(va.x, E2[2 * k + 0], c0);
            c1 = fma_f32x2(va.y, E2[2 * k + 1], c1);
            a2 = fma_f32x2(ub.x, E2[2 * k + 2], a2);
            a3 = fma_f32x2(ub.y, E2[2 * k + 3], a3);
            c2 = fma_f32x2(vb.x, E2[2 * k + 2], c2);
            c3 = fma_f32x2(vb.y, E2[2 * k + 3], c3);
        }
        unsigned long long sa = add_f32x2(add_f32x2(a0, a1), add_f32x2(a2, a3));
        unsigned long long sc = add_f32x2(add_f32x2(c0, c1), add_f32x2(c2, c3));
        float sa_lo, sa_hi, sc_lo, sc_hi;
        unpack_f32x2(sa, sa_lo, sa_hi);
        unpack_f32x2(sc, sc_lo, sc_hi);

        U0 = (sa_lo + sa_hi) * (r0 * ex0);
        U1 = (sc_lo + sc_hi) * (r1 * ex1);
        u_sh[nxt][0][j] = U0;
        u_sh[nxt][1][j] = U1;
        if (tid == ((t & 3) << 5)) {               // rotate MUFU log owner
            alog0 += __logf(r0);
            alog1 += __logf(r1);
        }
        cur = nxt;
        __syncthreads();
    }

    // ---------------- loop B: only batch 0 active (len1 <= t < len0) ----
    for (; t < len0; t++) {
        const int nxt = cur ^ 1;
        const float r0  = rcp_approx(u_sh[cur][0][0]);
        const float ex0 = __expf(xA0);

        xA0 = xB0;
        xp0 += LDIM; if (xp0 > xend0) xp0 = xend0;
        xB0 = *xp0;

        const ulonglong2* p0 = (const ulonglong2*)u_sh[cur][0];
        unsigned long long a0 = 0ull, a1 = 0ull, a2 = 0ull, a3 = 0ull;
        #pragma unroll
        for (int k = 0; k < 32; k += 2) {
            ulonglong2 ua = p0[k];
            ulonglong2 ub = p0[k + 1];
            a0 = fma_f32x2(ua.x, E2[2 * k + 0], a0);
            a1 = fma_f32x2(ua.y, E2[2 * k + 1], a1);
            a2 = fma_f32x2(ub.x, E2[2 * k + 2], a2);
            a3 = fma_f32x2(ub.y, E2[2 * k + 3], a3);
        }
        unsigned long long sa = add_f32x2(add_f32x2(a0, a1), add_f32x2(a2, a3));
        float sa_lo, sa_hi;
        unpack_f32x2(sa, sa_lo, sa_hi);

        U0 = (sa_lo + sa_hi) * (r0 * ex0);
        u_sh[nxt][0][j] = U0;
        if (tid == ((t & 3) << 5))
            alog0 += __logf(r0);
        cur = nxt;
        __syncthreads();
    }

    // ---------------- outputs ------------------------------------------
    float es0 = U0, es1 = U1;
    #pragma unroll
    for (int o = 16; o > 0; o >>= 1) {
        es0 += __shfl_xor_sync(0xffffffffu, es0, o);
        es1 += __shfl_xor_sync(0xffffffffu, es1, o);
    }
    if (l == 0) {
        wred[0][w] = es0;
        wred[1][w] = es1;
        wlog[0][w] = alog0;
        wlog[1][w] = alog1;
    }
    __syncthreads();
    if (tid == 0) {
        float ss0 = (wred[0][0] + wred[0][1]) + (wred[0][2] + wred[0][3]);
        float al0 = (wlog[0][0] + wlog[0][1]) + (wlog[0][2] + wlog[0][3]);
        out[b0] = X00 - al0 + logf(ss0) - s_ls[0];
        if (has_b1) {
            float ss1 = (wred[1][0] + wred[1][1]) + (wred[1][2] + wred[1][3]);
            float al1 = (wlog[1][0] + wlog[1][1]) + (wlog[1][2] + wlog[1][3]);
            out[b1] = X01 - al1 + logf(ss1) - s_ls[1];
        }
    }
}

extern "C" void kernel_launch(void* const* d_in, const int* in_sizes, int n_in,
                              void* d_out, int out_size)
{
    const float* input  = (const float*)d_in[0];   // (B, S, L) f32
    const int*   label  = (const int*)  d_in[1];   // (B, S) i32
    const int*   length = (const int*)  d_in[2];   // (B,) i32
    const float* trans  = (const float*)d_in[3];   // (L, L) f32
    float* out = (float*)d_out;                    // (B, 1) f32

    const int B = in_sizes[2];
    const int S = in_sizes[1] / B;

    // Target grid = 2 CTAs x 148 SMs = 296 blocks when possible.
    const int SLOTS = 296;
    int nblk, nsingle;
    const int minblk = (B + 1) / 2;      // all-pairs lower bound
    if (B >= SLOTS) {
        // choose nblk in [minblk, B] closest to SLOTS
        nblk = SLOTS < minblk ? minblk : SLOTS;
        if (nblk > B) nblk = B;
        nsingle = 2 * nblk - B;          // #blocks that get only one batch
        if (nsingle < 0) { nblk = minblk; nsingle = 2 * nblk - B; }
    } else {
        nblk = B;                        // every batch its own block
        nsingle = B;
    }

    sort_len_kernel<<<1, 1024>>>(length, B, S);
    crf_forward_kernel<<<nblk, 128>>>(input, label, length, trans, out,
                                      S, B, nsingle);
}

// round 8
// speedup vs baseline: 1.0376x; 1.0376x over previous
#include <cuda_runtime.h>
#include <math.h>
#include <limits.h>

// CRF loss: out[b] = logZ(b) - label_score(b).  B=512, S=512, L=128.
//
// Scaled linear-space forward recursion. One block of 256 threads handles
// TWO adjacent-length batches. Thread layout: warp w lane l -> column
// j = 16w + (l&15), half h = l>>4. Thread (j,h) holds E rows
// [64h, 64h+64) of column j as 32 f32x2 regs and computes BOTH batches'
// half-GEMVs (independent FFMA2 chains); halves combine with one
// shfl_xor(16) per batch. Thread (j,h) owns batch h's scalars: x prefetch,
// exp, rcp scale, U store. U double-buffered in bank-skewed shared
// (all LDS/STS single-wavefront), ONE __syncthreads per step.
// ~115 regs -> 2 CTAs/SM -> 16 warps/SM (4 per SMSP).
// Pairs sorted longest-first; co-resident blocks get complementary work.

#define LDIM 128

__device__ int d_perm[1024];

__device__ __forceinline__ unsigned long long pack_f32x2(float lo, float hi) {
    unsigned long long r;
    asm("mov.b64 %0, {%1, %2};" : "=l"(r) : "f"(lo), "f"(hi));
    return r;
}
__device__ __forceinline__ void unpack_f32x2(unsigned long long v, float& lo, float& hi) {
    asm("mov.b64 {%0, %1}, %2;" : "=f"(lo), "=f"(hi) : "l"(v));
}
__device__ __forceinline__ unsigned long long fma_f32x2(unsigned long long a,
                                                        unsigned long long b,
                                                        unsigned long long c) {
    unsigned long long d;
    asm("fma.rn.f32x2 %0, %1, %2, %3;" : "=l"(d) : "l"(a), "l"(b), "l"(c));
    return d;
}
__device__ __forceinline__ unsigned long long add_f32x2(unsigned long long a,
                                                        unsigned long long b) {
    unsigned long long d;
    asm("add.rn.f32x2 %0, %1, %2;" : "=l"(d) : "l"(a), "l"(b));
    return d;
}
__device__ __forceinline__ float rcp_approx(float x) {
    float r;
    asm("rcp.approx.ftz.f32 %0, %1;" : "=f"(r) : "f"(x));
    return r;
}

// ------------- longest-first permutation (bitonic, 1 block) ---------------
__global__ void sort_len_kernel(const int* __restrict__ length, int B, int S)
{
    __shared__ int key[1024];
    __shared__ int val[1024];
    const int t = threadIdx.x;

    int k = INT_MAX;
    if (t < B) {
        int L = length[t];
        L = L < 1 ? 1 : (L > S ? S : L);
        k = -L;               // ascending on -len => longest first
    }
    key[t] = k;
    val[t] = t;
    __syncthreads();

    for (int kk = 2; kk <= 1024; kk <<= 1) {
        for (int s = kk >> 1; s > 0; s >>= 1) {
            int p = t ^ s;
            if (p > t) {
                bool up = ((t & kk) == 0);
                int kt = key[t], kp = key[p];
                if ((kt > kp) == up) {
                    key[t] = kp; key[p] = kt;
                    int vt = val[t]; val[t] = val[p]; val[p] = vt;
                }
            }
            __syncthreads();
        }
    }
    if (t < B) d_perm[t] = val[t];
}

// ------------------------------ main kernel --------------------------------
__global__ __launch_bounds__(256, 2)
void crf_forward_kernel(const float* __restrict__ input,
                        const int*   __restrict__ label,
                        const int*   __restrict__ length,
                        const float* __restrict__ trans,
                        float* __restrict__ out,
                        int S, int B, int npairs, int nfirst)
{
    // g-stride 144 floats (bank +16) and +4-float skew at j>=64 keep every
    // broadcast LDS.128 / STS.32 pattern a single conflict-free wavefront.
    __shared__ __align__(16) float u_sh[2][2][144];
    __shared__ float wred[2][8];
    __shared__ float wlog[2][8];
    __shared__ float s_x00[2];
    __shared__ float s_ls[2];

    const int tid = threadIdx.x;
    const int w   = tid >> 5;
    const int l   = tid & 31;
    const int h   = l >> 4;              // half of i-range AND owned batch
    const int j   = w * 16 + (l & 15);   // state column 0..127

    // co-residency remap: blocks sharing an SM (bid, bid+148) get pairs
    // (p, npairs-1-p) -> complementary work.
    const int bid = blockIdx.x;
    const int pid = (bid < nfirst) ? bid : (npairs - 1 - (bid - nfirst));

    const int  b0   = d_perm[2 * pid];
    const bool has1 = (2 * pid + 1 < B);
    const int  b1   = has1 ? d_perm[2 * pid + 1] : b0;

    int len0 = length[b0]; len0 = len0 < 1 ? 1 : (len0 > S ? S : len0);
    int len1 = len0;
    if (has1) { len1 = length[b1]; len1 = len1 < 1 ? 1 : (len1 > S ? S : len1); }
    // sorted order guarantees len0 >= len1.

    const float* xb0 = input + (size_t)b0 * S * LDIM;
    const float* xb1 = input + (size_t)b1 * S * LDIM;
    const float* xbm = h ? xb1 : xb0;    // own batch
    const int    lenm = h ? len1 : len0;

    // ---------------- label scores (both batches) ----------------------
    #pragma unroll
    for (int g = 0; g < 2; g++) {
        const float* xb = g ? xb1 : xb0;
        const int* labb = label + (size_t)(g ? b1 : b0) * S;
        const int  len  = g ? (has1 ? len1 : 0) : len0;
        float ls = 0.f;
        for (int t = tid; t < len; t += 256) {
            int lab = labb[t];
            ls += xb[(size_t)t * LDIM + lab];
            if (t + 1 < len) ls += trans[lab * LDIM + labb[t + 1]];
        }
        #pragma unroll
        for (int o = 16; o > 0; o >>= 1)
            ls += __shfl_xor_sync(0xffffffffu, ls, o);
        if (l == 0) wred[g][w] = ls;
    }
    __syncthreads();
    if (tid < 2) {
        float acc = 0.f;
        #pragma unroll
        for (int i = 0; i < 8; i++) acc += wred[tid][i];
        s_ls[tid] = acc;
    }

    // ------ E rows [64h, 64h+64) of column j: 32 f32x2 registers -------
    unsigned long long E2[32];
    #pragma unroll
    for (int k = 0; k < 32; k++) {
        int i0 = 64 * h + 2 * k;
        float lo = __expf(trans[(i0)     * LDIM + j]);
        float hi = __expf(trans[(i0 + 1) * LDIM + j]);
        E2[k] = pack_f32x2(lo, hi);
    }

    // ---------------- init U (own batch) --------------------------------
    const int widx = j + ((j >> 6) << 2);      // skewed store index
    float x0 = xbm[j];
    if (tid == 0)  s_x00[0] = x0;              // j==0, h==0
    if (tid == 16) s_x00[1] = x0;              // j==0, h==1
    __syncthreads();
    const float X0m = s_x00[h];
    float U = __expf(x0 - X0m);
    u_sh[0][h][widx] = U;

    // prefetch own batch's x, 2 steps deep, clamped incrementing pointer
    const float* xend = xbm + (size_t)(lenm - 1) * LDIM + j;
    const float* xp = xbm + j + LDIM; if (xp > xend) xp = xend;
    float xA = *xp;                              // x for t=1
    xp += LDIM; if (xp > xend) xp = xend;
    float xB = *xp;                              // x for t=2

    float alog = 0.f;                            // rotating owners
    const int hoff = 68 * h;                     // skewed read base (floats)
    __syncthreads();

    int cur = 0;
    int t = 1;

    // ---------------- loop A: both batches active (t < len1) ------------
    for (; t < len1; t++) {
        const int nxt = cur ^ 1;
        const float r  = rcp_approx(u_sh[cur][h][0]);   // own batch's U[0]
        const float ex = __expf(xA);

        xA = xB;
        xp += LDIM; if (xp > xend) xp = xend;
        xB = *xp;

        const ulonglong2* q0 = (const ulonglong2*)(&u_sh[cur][0][0] + hoff);
        const ulonglong2* q1 = (const ulonglong2*)(&u_sh[cur][1][0] + hoff);
        unsigned long long a0 = 0ull, a1 = 0ull, a2 = 0ull, a3 = 0ull;
        unsigned long long c0 = 0ull, c1 = 0ull, c2 = 0ull, c3 = 0ull;
        #pragma unroll
        for (int k = 0; k < 16; k += 2) {
            ulonglong2 ua = q0[k];
            ulonglong2 ub = q0[k + 1];
            ulonglong2 va = q1[k];
            ulonglong2 vb = q1[k + 1];
            a0 = fma_f32x2(ua.x, E2[2 * k + 0], a0);
            a1 = fma_f32x2(ua.y, E2[2 * k + 1], a1);
            c0 = fma_f32x2(va.x, E2[2 * k + 0], c0);
            c1 = fma_f32x2(va.y, E2[2 * k + 1], c1);
            a2 = fma_f32x2(ub.x, E2[2 * k + 2], a2);
            a3 = fma_f32x2(ub.y, E2[2 * k + 3], a3);
            c2 = fma_f32x2(vb.x, E2[2 * k + 2], c2);
            c3 = fma_f32x2(vb.y, E2[2 * k + 3], c3);
        }
        unsigned long long sa = add_f32x2(add_f32x2(a0, a1), add_f32x2(a2, a3));
        unsigned long long sc = add_f32x2(add_f32x2(c0, c1), add_f32x2(c2, c3));
        float sa_lo, sa_hi, sc_lo, sc_hi;
        unpack_f32x2(sa, sa_lo, sa_hi);
        unpack_f32x2(sc, sc_lo, sc_hi);
        float s0 = sa_lo + sa_hi;
        float s1 = sc_lo + sc_hi;

        // combine halves (lane bit 4)
        s0 += __shfl_xor_sync(0xffffffffu, s0, 16);
        s1 += __shfl_xor_sync(0xffffffffu, s1, 16);

        U = (h ? s1 : s0) * (r * ex);
        u_sh[nxt][h][widx] = U;
        if (l == (h << 4) && w == (t & 7))       // rotate MUFU log owner
            alog += __logf(r);
        cur = nxt;
        __syncthreads();
    }

    // ---------------- loop B: only batch 0 active (len1 <= t < len0) ----
    for (; t < len0; t++) {
        const int nxt = cur ^ 1;
        const float r  = rcp_approx(u_sh[cur][0][0]);
        const float ex = __expf(xA);             // valid only for h==0

        if (h == 0) {
            xA = xB;
            xp += LDIM; if (xp > xend) xp = xend;
            xB = *xp;
        }

        const ulonglong2* q0 = (const ulonglong2*)(&u_sh[cur][0][0] + hoff);
        unsigned long long a0 = 0ull, a1 = 0ull, a2 = 0ull, a3 = 0ull;
        #pragma unroll
        for (int k = 0; k < 16; k += 2) {
            ulonglong2 ua = q0[k];
            ulonglong2 ub = q0[k + 1];
            a0 = fma_f32x2(ua.x, E2[2 * k + 0], a0);
            a1 = fma_f32x2(ua.y, E2[2 * k + 1], a1);
            a2 = fma_f32x2(ub.x, E2[2 * k + 2], a2);
            a3 = fma_f32x2(ub.y, E2[2 * k + 3], a3);
        }
        unsigned long long sa = add_f32x2(add_f32x2(a0, a1), add_f32x2(a2, a3));
        float sa_lo, sa_hi;
        unpack_f32x2(sa, sa_lo, sa_hi);
        float s0 = sa_lo + sa_hi;
        s0 += __shfl_xor_sync(0xffffffffu, s0, 16);

        if (h == 0) {
            U = s0 * (r * ex);
            u_sh[nxt][0][widx] = U;
        }
        if (l == 0 && w == (t & 7))
            alog += __logf(r);
        cur = nxt;
        __syncthreads();
    }

    // ---------------- outputs ------------------------------------------
    // thread (j,h) holds final U of batch h at column j
    float es = U;
    #pragma unroll
    for (int o = 8; o > 0; o >>= 1)              // reduce within 16-lane half
        es += __shfl_xor_sync(0xffffffffu, es, o);
    if ((l & 15) == 0) {
        wred[h][w] = es;
        wlog[h][w] = alog;
    }
    __syncthreads();
    if (tid == 0) {
        float ss0 = 0.f, al0 = 0.f;
        #pragma unroll
        for (int i = 0; i < 8; i++) { ss0 += wred[0][i]; al0 += wlog[0][i]; }
        out[b0] = s_x00[0] - al0 + logf(ss0) - s_ls[0];
        if (has1) {
            float ss1 = 0.f, al1 = 0.f;
            #pragma unroll
            for (int i = 0; i < 8; i++) { ss1 += wred[1][i]; al1 += wlog[1][i]; }
            out[b1] = s_x00[1] - al1 + logf(ss1) - s_ls[1];
        }
    }
}

extern "C" void kernel_launch(void* const* d_in, const int* in_sizes, int n_in,
                              void* d_out, int out_size)
{
    const float* input  = (const float*)d_in[0];   // (B, S, L) f32
    const int*   label  = (const int*)  d_in[1];   // (B, S) i32
    const int*   length = (const int*)  d_in[2];   // (B,) i32
    const float* trans  = (const float*)d_in[3];   // (L, L) f32
    float* out = (float*)d_out;                    // (B, 1) f32

    const int B = in_sizes[2];
    const int S = in_sizes[1] / B;

    const int npairs = (B + 1) / 2;
    const int nfirst = npairs > 148 ? 148 : npairs;

    sort_len_kernel<<<1, 1024>>>(length, B, S);
    crf_forward_kernel<<<npairs, 256>>>(input, label, length, trans, out,
                                        S, B, npairs, nfirst);
}